// round 8
// baseline (speedup 1.0000x reference)
#include <cuda_runtime.h>
#include <cuda_fp16.h>
#include <cstdint>
#include <cstddef>

// Problem constants
static constexpr int NN = 65536;
static constexpr int MROWS = 2 * NN;     // 131072 token rows
static constexpr int NBLK = MROWS / 128; // 1024 blocks

// ---------------- device scratch ----------------
// Combined per-head weights: [k=256][h*128 + (0..63: W_fx_h | 64..127: W_x_h@W_slice)]
__device__ __half g_Wcomb[256 * 1024];
__device__ float  g_biasL[8 * 64];        // b_x_h @ W_slice + b_slice
__device__ float  g_invtemp[8];
__device__ __half g_Part[(size_t)NBLK * 8 * 4096]; // 64 MB fp16 partials
__device__ float  g_PartN[NBLK * 8 * 64];

// ---------------- ptx helpers ----------------
__device__ __forceinline__ uint32_t smem_u32(const void* p) {
    return (uint32_t)__cvta_generic_to_shared(p);
}
__device__ __forceinline__ void ldm_x4(uint32_t* r, uint32_t addr) {
    asm volatile("ldmatrix.sync.aligned.m8n8.x4.shared.b16 {%0,%1,%2,%3}, [%4];"
                 : "=r"(r[0]), "=r"(r[1]), "=r"(r[2]), "=r"(r[3]) : "r"(addr));
}
__device__ __forceinline__ void ldm_x4_t(uint32_t* r, uint32_t addr) {
    asm volatile("ldmatrix.sync.aligned.m8n8.x4.trans.shared.b16 {%0,%1,%2,%3}, [%4];"
                 : "=r"(r[0]), "=r"(r[1]), "=r"(r[2]), "=r"(r[3]) : "r"(addr));
}
__device__ __forceinline__ void mma_f16(float* c, const uint32_t* a, uint32_t b0, uint32_t b1) {
    asm volatile("mma.sync.aligned.m16n8k16.row.col.f32.f16.f16.f32 "
                 "{%0,%1,%2,%3}, {%4,%5,%6,%7}, {%8,%9}, {%0,%1,%2,%3};"
                 : "+f"(c[0]), "+f"(c[1]), "+f"(c[2]), "+f"(c[3])
                 : "r"(a[0]), "r"(a[1]), "r"(a[2]), "r"(a[3]), "r"(b0), "r"(b1));
}
__device__ __forceinline__ void cp16(uint32_t smem_addr, const void* gptr) {
    asm volatile("cp.async.cg.shared.global [%0], [%1], 16;"
                 :: "r"(smem_addr), "l"(gptr) : "memory");
}
__device__ __forceinline__ void cp_commit() {
    asm volatile("cp.async.commit_group;" ::: "memory");
}
__device__ __forceinline__ void cp_wait0() {
    asm volatile("cp.async.wait_group 0;" ::: "memory");
}

// ---------------- K1: weight prep (fold W_slice into W_x) ----------------
__global__ void __launch_bounds__(256) prep_kernel(
        const float* __restrict__ Wx,  const float* __restrict__ bx,
        const float* __restrict__ Wfx, const float* __restrict__ bfx,
        const float* __restrict__ Wsl, const float* __restrict__ bsl,
        const float* __restrict__ temp) {
    int idx = blockIdx.x * blockDim.x + threadIdx.x;   // 0..262143
    int k = idx >> 10, j = idx & 1023;
    int h = j >> 7, c = j & 127;
    if (c < 64) {
        g_Wcomb[k * 1024 + h * 128 + c] = __float2half(Wfx[k * 512 + h * 64 + c]);
    } else {
        int s = c - 64;
        float acc = 0.f;
        #pragma unroll 8
        for (int d = 0; d < 64; d++)
            acc += Wx[k * 512 + h * 64 + d] * Wsl[d * 64 + s];
        g_Wcomb[k * 1024 + h * 128 + c] = __float2half(acc);
    }
    if (idx < 512) {
        int hh = idx >> 6, s = idx & 63;
        float a = bsl[s];
        #pragma unroll 8
        for (int d = 0; d < 64; d++)
            a += bx[hh * 64 + d] * Wsl[d * 64 + s];
        g_biasL[hh * 64 + s] = a;
    }
    if (idx < 8) {
        float t = temp[idx];
        t = fminf(fmaxf(t, 0.5f), 5.0f);
        g_invtemp[idx] = 1.0f / t;
    }
}

// ---------------- fused kernel ----------------
// 1024 blocks x 512 threads (16 warps, grid 8x2, warp tile 16x64).
// Per head: GEMM [128 tok]x[f|logits] -> even warps store f, odd warps do
// register softmax -> agg mma (w^T @ f) -> partials. B(h+1) prefetched via cp.async.
static constexpr int ASTR = 264, BSTR = 136, FSTR = 72, WGSTR = 72;
static constexpr int OFF_AS   = 0;
static constexpr int OFF_BS   = OFF_AS + 128 * ASTR * 2;     // 67584
static constexpr int OFF_FS   = OFF_BS + 256 * BSTR * 2;     // +69632
static constexpr int OFF_WGT  = OFF_FS + 128 * FSTR * 2;     // +18432
static constexpr int OFF_BF   = OFF_WGT + 128 * WGSTR * 2;   // +18432: biasF 8x64 f32
static constexpr int OFF_BL   = OFF_BF + 2048;               // biasL 8x64 f32
static constexpr int OFF_IT   = OFF_BL + 2048;               // invtemp 8 f32
static constexpr int OFF_NRM  = OFF_IT + 32;                 // 64 f32
static constexpr int FUSED_SMEM = OFF_NRM + 256;             // ~178.7 KB

__global__ void __launch_bounds__(512) fused_kernel(const float* __restrict__ x,
                                                    const float* __restrict__ bfx) {
    extern __shared__ char smem[];
    __half* As   = (__half*)(smem + OFF_AS);
    __half* Bs   = (__half*)(smem + OFF_BS);
    __half* Fs   = (__half*)(smem + OFF_FS);
    __half* Wgt  = (__half*)(smem + OFF_WGT);
    float*  bfS  = (float*)(smem + OFF_BF);
    float*  blS  = (float*)(smem + OFF_BL);
    float*  itS  = (float*)(smem + OFF_IT);
    float*  nrm  = (float*)(smem + OFF_NRM);
    const uint32_t bs_u32 = smem_u32(Bs);

    const int tid = threadIdx.x, warpid = tid >> 5, lane = tid & 31;
    const int blk = blockIdx.x;
    const float* xrow = x + (size_t)blk * 128 * 256;

    // prologue: prefetch B(0)  (64KB: 4096 x 16B, 8 per thread)
    {
        #pragma unroll
        for (int i = 0; i < 8; i++) {
            int e = tid + i * 512;           // chunk id
            int k = e >> 4, c8 = (e & 15) * 8;
            cp16(bs_u32 + (k * BSTR + c8) * 2, g_Wcomb + k * 1024 + 0 * 128 + c8);
        }
        cp_commit();
    }

    // stage X tile (fp32 -> fp16)
    for (int i = tid; i < 128 * 64; i += 512) {
        int r = i >> 6, c4 = (i & 63) * 4;
        float4 v = *(const float4*)(xrow + r * 256 + c4);
        __half2* dst = (__half2*)(As + r * ASTR + c4);
        dst[0] = __floats2half2_rn(v.x, v.y);
        dst[1] = __floats2half2_rn(v.z, v.w);
    }
    // stage biases
    for (int i = tid; i < 512; i += 512) {
        bfS[i] = bfx[i];
        blS[i] = g_biasL[i];
    }
    if (tid < 8)  itS[tid] = g_invtemp[tid];
    if (tid < 64) nrm[tid] = 0.f;

    const int wm = warpid >> 1, wn = warpid & 1;      // GEMM 8x2 warp grid
    const int sbase = (warpid >> 2) * 16, dbase = (warpid & 3) * 16;  // agg tiles

    for (int h = 0; h < 8; h++) {
        cp_wait0();
        __syncthreads();   // Bs(h) visible to all; Fs/Wgt/nrm free

        // ---- GEMM: [128 tok] x [128 (f|logit)], K=256, warp tile 16x64 ----
        float acc[8][4];
        #pragma unroll
        for (int ni = 0; ni < 8; ni++)
            #pragma unroll
            for (int q = 0; q < 4; q++) acc[ni][q] = 0.f;

        #pragma unroll
        for (int kk = 0; kk < 256; kk += 16) {
            uint32_t a[4], bfr[4][4];
            ldm_x4(a, smem_u32(As + (wm * 16 + (lane & 15)) * ASTR + kk + (lane >> 4) * 8));
            #pragma unroll
            for (int p = 0; p < 4; p++) {
                int col = wn * 64 + p * 16 + (lane >> 4) * 8;
                ldm_x4_t(bfr[p], smem_u32(Bs + (kk + (lane & 15)) * BSTR + col));
            }
            #pragma unroll
            for (int ni = 0; ni < 8; ni++)
                mma_f16(acc[ni], a, bfr[ni >> 1][(ni & 1) * 2], bfr[ni >> 1][(ni & 1) * 2 + 1]);
        }

        // ---- epilogue ----
        if (wn == 0) {
            // f columns: +bias_f -> Fs
            int r0 = wm * 16 + (lane >> 2);
            #pragma unroll
            for (int ni = 0; ni < 8; ni++) {
                int c = ni * 8 + (lane & 3) * 2;
                float b0 = bfS[h * 64 + c], b1 = bfS[h * 64 + c + 1];
                *(__half2*)(Fs + r0 * FSTR + c) =
                    __floats2half2_rn(acc[ni][0] + b0, acc[ni][1] + b1);
                *(__half2*)(Fs + (r0 + 8) * FSTR + c) =
                    __floats2half2_rn(acc[ni][2] + b0, acc[ni][3] + b1);
            }
        } else {
            // logits: +bias_l, *invt, register softmax over 64 slices
            const float invt = itS[h];
            float mA = -1e30f, mB = -1e30f;
            #pragma unroll
            for (int f = 0; f < 8; f++) {
                int c = f * 8 + (lane & 3) * 2;
                float b0 = blS[h * 64 + c], b1 = blS[h * 64 + c + 1];
                acc[f][0] = (acc[f][0] + b0) * invt;
                acc[f][1] = (acc[f][1] + b1) * invt;
                acc[f][2] = (acc[f][2] + b0) * invt;
                acc[f][3] = (acc[f][3] + b1) * invt;
                mA = fmaxf(mA, fmaxf(acc[f][0], acc[f][1]));
                mB = fmaxf(mB, fmaxf(acc[f][2], acc[f][3]));
            }
            #pragma unroll
            for (int off = 1; off <= 2; off <<= 1) {
                mA = fmaxf(mA, __shfl_xor_sync(0xffffffffu, mA, off));
                mB = fmaxf(mB, __shfl_xor_sync(0xffffffffu, mB, off));
            }
            float sA = 0.f, sB = 0.f;
            #pragma unroll
            for (int f = 0; f < 8; f++) {
                acc[f][0] = __expf(acc[f][0] - mA);
                acc[f][1] = __expf(acc[f][1] - mA);
                acc[f][2] = __expf(acc[f][2] - mB);
                acc[f][3] = __expf(acc[f][3] - mB);
                sA += acc[f][0] + acc[f][1];
                sB += acc[f][2] + acc[f][3];
            }
            #pragma unroll
            for (int off = 1; off <= 2; off <<= 1) {
                sA += __shfl_xor_sync(0xffffffffu, sA, off);
                sB += __shfl_xor_sync(0xffffffffu, sB, off);
            }
            const float iA = 1.f / sA, iB = 1.f / sB;
            const int rA = wm * 16 + (lane >> 2);
            float ncol[8][2];
            #pragma unroll
            for (int f = 0; f < 8; f++) {
                float w0 = acc[f][0] * iA, w1 = acc[f][1] * iA;
                float w2 = acc[f][2] * iB, w3 = acc[f][3] * iB;
                int c = f * 8 + (lane & 3) * 2;
                *(__half2*)(Wgt + rA * WGSTR + c)       = __floats2half2_rn(w0, w1);
                *(__half2*)(Wgt + (rA + 8) * WGSTR + c) = __floats2half2_rn(w2, w3);
                ncol[f][0] = w0 + w2;
                ncol[f][1] = w1 + w3;
            }
            #pragma unroll
            for (int f = 0; f < 8; f++) {
                #pragma unroll
                for (int off = 4; off <= 16; off <<= 1) {
                    ncol[f][0] += __shfl_xor_sync(0xffffffffu, ncol[f][0], off);
                    ncol[f][1] += __shfl_xor_sync(0xffffffffu, ncol[f][1], off);
                }
            }
            if (lane < 4) {
                #pragma unroll
                for (int f = 0; f < 8; f++) {
                    int c = f * 8 + lane * 2;
                    atomicAdd(&nrm[c], ncol[f][0]);
                    atomicAdd(&nrm[c + 1], ncol[f][1]);
                }
            }
        }
        __syncthreads();   // Fs/Wgt/nrm complete; Bs reads done

        // prefetch B(h+1) over the agg phase
        if (h < 7) {
            #pragma unroll
            for (int i = 0; i < 8; i++) {
                int e = tid + i * 512;
                int k = e >> 4, c8 = (e & 15) * 8;
                cp16(bs_u32 + (k * BSTR + c8) * 2, g_Wcomb + k * 1024 + (h + 1) * 128 + c8);
            }
            cp_commit();
        }

        // ---- aggregation: out[s,d] = sum_t w[t,s] * f[t,d] ----
        float ag[2][4];
        #pragma unroll
        for (int ng = 0; ng < 2; ng++)
            #pragma unroll
            for (int q = 0; q < 4; q++) ag[ng][q] = 0.f;

        #pragma unroll
        for (int kk = 0; kk < 128; kk += 16) {
            uint32_t a[4], bb[4];
            int trow = kk + (lane & 7) + ((lane >> 4) << 3);
            int scol = sbase + (((lane >> 3) & 1) << 3);
            ldm_x4_t(a, smem_u32(Wgt + trow * WGSTR + scol));
            ldm_x4_t(bb, smem_u32(Fs + (kk + (lane & 15)) * FSTR + dbase + (lane >> 4) * 8));
            mma_f16(ag[0], a, bb[0], bb[1]);
            mma_f16(ag[1], a, bb[2], bb[3]);
        }
        __half* pt = g_Part + ((size_t)(blk * 8 + h)) * 4096;
        #pragma unroll
        for (int ng = 0; ng < 2; ng++) {
            int s = sbase + (lane >> 2);
            int d = dbase + ng * 8 + (lane & 3) * 2;
            *(__half2*)(pt + s * 64 + d)       = __floats2half2_rn(ag[ng][0], ag[ng][1]);
            *(__half2*)(pt + (s + 8) * 64 + d) = __floats2half2_rn(ag[ng][2], ag[ng][3]);
        }
        if (tid < 64) {
            g_PartN[(blk * 8 + h) * 64 + tid] = nrm[tid];
            nrm[tid] = 0.f;
        }
        __syncthreads();   // protect Wgt/Fs/nrm for next head
    }
}

// ---------------- reduce ----------------
__global__ void __launch_bounds__(256) reduce_kernel(float* __restrict__ out) {
    const int bid = blockIdx.x;         // 256: bh x 16 s-chunks
    const int bh = bid >> 4, sc = bid & 15;
    const int b = bh >> 3, h = bh & 7;
    __shared__ float invn[4];
    const int tid = threadIdx.x, warpid = tid >> 5, lane = tid & 31;

    if (warpid < 4) {
        int s = sc * 4 + warpid;
        float p = 0.f;
        for (int i = lane; i < 512; i += 32)
            p += g_PartN[((b * 512 + i) * 8 + h) * 64 + s];
        #pragma unroll
        for (int off = 16; off > 0; off >>= 1)
            p += __shfl_xor_sync(0xffffffffu, p, off);
        if (lane == 0) invn[warpid] = 1.f / (p + 0.01f);
    }
    __syncthreads();

    const int sl = tid >> 6, d = tid & 63;
    const int s = sc * 4 + sl;
    float sum = 0.f;
    #pragma unroll 8
    for (int i = 0; i < 512; i++)
        sum += __half2float(g_Part[((size_t)((b * 512 + i) * 8 + h)) * 4096 + s * 64 + d]);
    out[bh * 4096 + s * 64 + d] = sum * invn[sl];
}

__global__ void nop_kernel() {}

// ---------------- launch: fused is 4th launch so ncu skip-5 profiles it ----------------
extern "C" void kernel_launch(void* const* d_in, const int* in_sizes, int n_in,
                              void* d_out, int out_size) {
    const float* x    = (const float*)d_in[0];
    const float* Wx   = (const float*)d_in[1];
    const float* bx   = (const float*)d_in[2];
    const float* Wfx  = (const float*)d_in[3];
    const float* bfx  = (const float*)d_in[4];
    const float* Wsl  = (const float*)d_in[5];
    const float* bsl  = (const float*)d_in[6];
    const float* temp = (const float*)d_in[7];

    cudaFuncSetAttribute(fused_kernel, cudaFuncAttributeMaxDynamicSharedMemorySize, FUSED_SMEM);

    prep_kernel<<<1024, 256>>>(Wx, bx, Wfx, bfx, Wsl, bsl, temp);
    nop_kernel<<<1, 32>>>();
    nop_kernel<<<1, 32>>>();
    fused_kernel<<<NBLK, 512, FUSED_SMEM>>>(x, bfx);
    reduce_kernel<<<256, 256>>>((float*)d_out);
}